// round 13
// baseline (speedup 1.0000x reference)
#include <cuda_runtime.h>
#include <cuda_bf16.h>
#include <cstdint>

// ---------------------------------------------------------------------------
// GraphConvLSTM on GB300 — Round 13: single-kernel. Gate projection fused
// into fused_kernel init (was a separate kernel + g_xg round-trip, ~47 us).
// Recurrence identical to R12: bf16 hi/lo mma (A=W^T), clique combine,
// tanh.approx epilogue, double-buffered h planes, 1 group-barrier per step.
// ---------------------------------------------------------------------------

#define BATCH   512
#define INDIM   256
#define HDIM    128
#define TSTEPS  100
#define NNODES  22
#define GROUPS  4

// smem word layout (4B words)
#define WPL_WORDS  (128 * 68)          // one W^T bf16 plane [j][kword], stride 68
#define HPL_WORDS  (24 * 68)           // one h bf16 plane [node][kword]
#define HBUF_BYTES (2 * HPL_WORDS * 4) // hi+lo pair, one buffer (13056 B)
#define P_STRIDE   28                  // p row stride: 112B, 16B-aligned, cf-free
#define P_WORDS    (128 * P_STRIDE)    // also hosts x staging (256 floats) at init
#define GRP_WORDS  (4 * HPL_WORDS + P_WORDS)              // 10112
#define TOT_WORDS  (2 * WPL_WORDS + GROUPS * GRP_WORDS)   // 57856 (226 KB)

// -------------------- clique-factored adjacency ------------------------------
__device__ constexpr int CLQ[5][6] = {
    {0,2,5,8,11,-1}, {0,1,4,7,10,-1}, {0,3,6,9,12,15},
    {9,14,17,19,21,-1}, {9,13,16,18,20,-1}
};
__device__ constexpr int CMASK[22] = {
    7,2,1,4,2,1,4,2,1,28,2,1,4,16,8,4,16,8,16,8,16,8
};
__device__ constexpr float CCNT[22] = {
    3.f,1.f,1.f,1.f,1.f,1.f,1.f,1.f,1.f,3.f,1.f,1.f,1.f,1.f,1.f,1.f,1.f,1.f,1.f,1.f,1.f,1.f
};
__device__ constexpr float DINV[22] = {
    0.2773500979f, 0.5f, 0.5f, 0.4472135955f, 0.5f, 0.5f, 0.4472135955f, 0.5f, 0.5f,
    0.2773500979f, 0.5f, 0.5f, 0.4472135955f, 0.5f, 0.5f, 0.4472135955f,
    0.5f, 0.5f, 0.5f, 0.5f, 0.5f, 0.5f
};

// -------------------- helpers ------------------------------------------------
__device__ __forceinline__ uint32_t pack_bf16(float a, float b) {
    __nv_bfloat162 v = __floats2bfloat162_rn(a, b);
    return *reinterpret_cast<uint32_t*>(&v);
}
__device__ __forceinline__ void split_bf16(float f, float& hi, float& lo) {
    __nv_bfloat16 h = __float2bfloat16(f);
    hi = __bfloat162float(h);
    lo = f - hi;
}
__device__ __forceinline__ float tanha(float x) {
    float r;
    asm("tanh.approx.f32 %0, %1;" : "=f"(r) : "f"(x));
    return r;
}
__device__ __forceinline__ float sig_h(float a) {   // sigmoid(2a)
    return fmaf(0.5f, tanha(a), 0.5f);
}
__device__ __forceinline__ uint32_t smem_u32(const void* p) {
    return static_cast<uint32_t>(__cvta_generic_to_shared(p));
}

#define MMA_BF16(D, A0, A1, A2, A3, B0, B1)                                    \
    asm volatile(                                                              \
        "mma.sync.aligned.m16n8k16.row.col.f32.bf16.bf16.f32 "                 \
        "{%0,%1,%2,%3}, {%4,%5,%6,%7}, {%8,%9}, {%0,%1,%2,%3};"                \
        : "+f"((D)[0]), "+f"((D)[1]), "+f"((D)[2]), "+f"((D)[3])               \
        : "r"(A0), "r"(A1), "r"(A2), "r"(A3), "r"(B0), "r"(B1))

#define LDSM_X4(R0, R1, R2, R3, ADDR)                                          \
    asm volatile(                                                              \
        "ldmatrix.sync.aligned.m8n8.x4.shared.b16 {%0,%1,%2,%3}, [%4];"        \
        : "=r"(R0), "=r"(R1), "=r"(R2), "=r"(R3) : "r"(ADDR))

// -------------------- fused: gates + recurrence -------------------------------
__global__ __launch_bounds__(512, 1) void fused_kernel(
    const float* __restrict__ x,
    const float* __restrict__ wi, const float* __restrict__ bi,
    const float* __restrict__ wf, const float* __restrict__ bf,
    const float* __restrict__ wo, const float* __restrict__ bo,
    const float* __restrict__ wc, const float* __restrict__ bc,
    const float* __restrict__ gw,
    const float* __restrict__ gb,
    float* __restrict__ out)
{
    extern __shared__ uint32_t smw[];
    uint32_t* wth = smw;                  // W^T hi plane [j][kword], stride 68
    uint32_t* wtl = smw + WPL_WORDS;      // W^T lo plane

    const int tid  = threadIdx.x;
    const int g    = tid >> 7;            // group 0..3
    const int ltid = tid & 127;           // column j
    const int lane = tid & 31;
    const int wig  = ltid >> 5;
    const int b    = blockIdx.x * GROUPS + g;

    // group layout: [hhi0|hlo0|hhi1|hlo1|ps]
    uint32_t* grp  = smw + 2 * WPL_WORDS + g * GRP_WORDS;
    uint32_t* hbuf = grp;                                   // 4 h planes
    float*    ps   = reinterpret_cast<float*>(grp + 4 * HPL_WORDS);

    // ---------- init A: W^T bf16 planes, zero h bufs, stage x ----------
    for (int idx = tid; idx < 128 * 64; idx += 512) {
        int jr = idx >> 6;
        int k2 = idx & 63;
        int k  = 2 * k2;
        float w0 = gw[k * HDIM + jr];
        float w1 = gw[(k + 1) * HDIM + jr];
        float h0, l0, h1, l1;
        split_bf16(w0, h0, l0);
        split_bf16(w1, h1, l1);
        wth[jr * 68 + k2] = pack_bf16(h0, h1);
        wtl[jr * 68 + k2] = pack_bf16(l0, l1);
    }
    for (int i = tid; i < GROUPS * 4 * HPL_WORDS; i += 512) {
        // zero only the h buffers of each group (first 4*HPL_WORDS of GRP)
        int gg = i / (4 * HPL_WORDS);
        int o  = i - gg * (4 * HPL_WORDS);
        smw[2 * WPL_WORDS + gg * GRP_WORDS + o] = 0u;
    }
    // stage x[b][0..256) into this group's ps region
    reinterpret_cast<float2*>(ps)[ltid] =
        reinterpret_cast<const float2*>(x + (size_t)b * INDIM)[ltid];
    __syncthreads();

    // ---------- init B: gate projection (thread = (batch b, column j)) -------
    // ai..ac accumulate in ascending k, single fp32 chain: identical rounding
    // to the former gate_kernel.
    float xi, xf, xo, xc;
    {
        float ai = 0.f, af = 0.f, ao = 0.f, ac = 0.f;
        const float4* wi4 = reinterpret_cast<const float4*>(wi + ltid * INDIM);
        const float4* wf4 = reinterpret_cast<const float4*>(wf + ltid * INDIM);
        const float4* wo4 = reinterpret_cast<const float4*>(wo + ltid * INDIM);
        const float4* wc4 = reinterpret_cast<const float4*>(wc + ltid * INDIM);
        const float4* xs4 = reinterpret_cast<const float4*>(ps);
#pragma unroll 8
        for (int k4 = 0; k4 < 64; k4++) {
            float4 xv = xs4[k4];
            float4 a = wi4[k4];
            ai = fmaf(xv.x, a.x, ai); ai = fmaf(xv.y, a.y, ai);
            ai = fmaf(xv.z, a.z, ai); ai = fmaf(xv.w, a.w, ai);
            float4 f = wf4[k4];
            af = fmaf(xv.x, f.x, af); af = fmaf(xv.y, f.y, af);
            af = fmaf(xv.z, f.z, af); af = fmaf(xv.w, f.w, af);
            float4 o = wo4[k4];
            ao = fmaf(xv.x, o.x, ao); ao = fmaf(xv.y, o.y, ao);
            ao = fmaf(xv.z, o.z, ao); ao = fmaf(xv.w, o.w, ao);
            float4 cc = wc4[k4];
            ac = fmaf(xv.x, cc.x, ac); ac = fmaf(xv.y, cc.y, ac);
            ac = fmaf(xv.z, cc.z, ac); ac = fmaf(xv.w, cc.w, ac);
        }
        float gbv = gb[ltid];
        xi = 0.5f * ((ai + bi[ltid]) + gbv);
        xf = 0.5f * ((af + bf[ltid]) + gbv);
        xo = 0.5f * ((ao + bo[ltid]) + gbv);
        xc = (ac + bc[ltid]) + gbv;
    }

    float c[NNODES];
#pragma unroll
    for (int m = 0; m < NNODES; m++) c[m] = 0.f;

    // A-fragment ldmatrix bases: [plane][mt]
    const int lq  = lane >> 2;
    const int kw  = lane & 3;
    const int wof = wig * 32;
    uint32_t a_base[2][2];
    {
        int arow = (lane & 7) + ((lane >> 3) & 1) * 8;
        int acol = ((lane >> 4) & 1) * 4;
#pragma unroll
        for (int p = 0; p < 2; p++) {
            const uint32_t* pl = p ? wtl : wth;
#pragma unroll
            for (int mt = 0; mt < 2; mt++)
                a_base[p][mt] = smem_u32(pl + (wof + mt * 16 + arow) * 68 + acol);
        }
    }
    // B-fragment ldmatrix bases for buffer 0: [plane][nt]; buffer 1 = +HBUF_BYTES
    uint32_t b_base[2][3];
    {
        int brow  = lane & 7;
        int bhalf = lane >> 3;            // 0..3
#pragma unroll
        for (int p = 0; p < 2; p++) {
            const uint32_t* pl = hbuf + p * HPL_WORDS;   // hhi0 / hlo0
#pragma unroll
            for (int nt = 0; nt < 3; nt++)
                b_base[p][nt] = smem_u32(pl + (nt * 8 + brow) * 68) + bhalf * 16;
        }
    }

    const int bar = g + 1;
    // group barrier: xs (in ps region) fully consumed before the loop's
    // p spill overwrites it
    asm volatile("bar.sync %0, 128;" :: "r"(bar) : "memory");

    // phase stagger: groups drift anti-phase so HMMA and MUFU bursts overlap
    __nanosleep(g * 2000u);

    for (int t = 0; t < TSTEPS; t++) {
        const uint32_t rbuf = (uint32_t)(t & 1) * HBUF_BYTES;      // read buffer
        uint32_t* whbuf = hbuf + ((t + 1) & 1) * 2 * HPL_WORDS;    // write buffer
        __nv_bfloat16* hhi_w = reinterpret_cast<__nv_bfloat16*>(whbuf);
        __nv_bfloat16* hlo_w = reinterpret_cast<__nv_bfloat16*>(whbuf + HPL_WORDS);

        // ---- mma phase: p^T(2mt x 3nt) = W^T(hi/lo) @ h(hi/lo), K=128 ----
        float acc[2][3][4];
#pragma unroll
        for (int mt = 0; mt < 2; mt++)
#pragma unroll
            for (int nt = 0; nt < 3; nt++)
#pragma unroll
                for (int q = 0; q < 4; q++) acc[mt][nt][q] = 0.f;

#pragma unroll
        for (int kp = 0; kp < 4; kp++) {          // pairs of k-steps
            uint32_t bh[3][4], bl[3][4];
#pragma unroll
            for (int nt = 0; nt < 3; nt++) {
                LDSM_X4(bh[nt][0], bh[nt][1], bh[nt][2], bh[nt][3],
                        b_base[0][nt] + rbuf + kp * 64);
                LDSM_X4(bl[nt][0], bl[nt][1], bl[nt][2], bl[nt][3],
                        b_base[1][nt] + rbuf + kp * 64);
            }
#pragma unroll
            for (int hf = 0; hf < 2; hf++) {      // kt = 2*kp + hf
                const uint32_t koff = (2 * kp + hf) * 32;
                uint32_t ah[2][4], al[2][4];
#pragma unroll
                for (int mt = 0; mt < 2; mt++) {
                    LDSM_X4(ah[mt][0], ah[mt][1], ah[mt][2], ah[mt][3],
                            a_base[0][mt] + koff);
                    LDSM_X4(al[mt][0], al[mt][1], al[mt][2], al[mt][3],
                            a_base[1][mt] + koff);
                }
#pragma unroll
                for (int nt = 0; nt < 3; nt++) {
                    uint32_t b0h = bh[nt][hf * 2], b1h = bh[nt][hf * 2 + 1];
                    uint32_t b0l = bl[nt][hf * 2], b1l = bl[nt][hf * 2 + 1];
#pragma unroll
                    for (int mt = 0; mt < 2; mt++) {
                        MMA_BF16(acc[mt][nt], ah[mt][0], ah[mt][1], ah[mt][2], ah[mt][3], b0h, b1h);
                        MMA_BF16(acc[mt][nt], ah[mt][0], ah[mt][1], ah[mt][2], ah[mt][3], b0l, b1l);
                        MMA_BF16(acc[mt][nt], al[mt][0], al[mt][1], al[mt][2], al[mt][3], b0h, b1h);
                    }
                }
            }
        }

        // ---- spill p fragments: ps[j][node] (intra-warp rows) ----
#pragma unroll
        for (int mt = 0; mt < 2; mt++) {
            int j0 = wof + mt * 16 + lq;
            int j1 = j0 + 8;
#pragma unroll
            for (int nt = 0; nt < 3; nt++) {
                int n0 = nt * 8 + (kw << 1);
                *reinterpret_cast<float2*>(&ps[j0 * P_STRIDE + n0]) =
                    make_float2(acc[mt][nt][0], acc[mt][nt][1]);
                *reinterpret_cast<float2*>(&ps[j1 * P_STRIDE + n0]) =
                    make_float2(acc[mt][nt][2], acc[mt][nt][3]);
            }
        }
        // p exchange is warp-local (warp wig owns ps rows [32*wig, 32*wig+32))
        __syncwarp();

        // ---- combine + epilogue: thread owns column j = ltid ----
        float p[NNODES];
        {
            const float4* pv = reinterpret_cast<const float4*>(&ps[ltid * P_STRIDE]);
#pragma unroll
            for (int q = 0; q < 5; q++) {
                float4 v = pv[q];
                p[q * 4 + 0] = v.x; p[q * 4 + 1] = v.y;
                if (q * 4 + 2 < NNODES) p[q * 4 + 2] = v.z;
                if (q * 4 + 3 < NNODES) p[q * 4 + 3] = v.w;
            }
            float2 v2 = *reinterpret_cast<const float2*>(&ps[ltid * P_STRIDE + 20]);
            p[20] = v2.x; p[21] = v2.y;
        }

        // clique sums
        float S[5];
#pragma unroll
        for (int cq = 0; cq < 5; cq++) {
            float s = 0.f;
#pragma unroll
            for (int e = 0; e < 6; e++) {
                if (CLQ[cq][e] >= 0) {
                    const int n = CLQ[cq][e];
                    s = fmaf(DINV[n], p[n], s);
                }
            }
            S[cq] = s;
        }

        float* ob = out + (((size_t)b * TSTEPS + t) * NNODES) * HDIM + ltid;
#pragma unroll
        for (int m = 0; m < NNODES; m++) {
            float s = 0.f;
#pragma unroll
            for (int cq = 0; cq < 5; cq++)
                if ((CMASK[m] >> cq) & 1) s += S[cq];
            float gacc = DINV[m] * (s - CCNT[m] * DINV[m] * p[m]);

            float hd = 0.5f * gacc;
            float it = sig_h(xi + hd);
            float ft = sig_h(xf + hd);
            float ot = sig_h(xo + hd);
            float ct = tanha(xc + gacc);
            float cn = fmaf(ft, c[m], it * ct);
            c[m] = cn;
            float hv = ot * tanha(cn);
            ob[m * HDIM] = hv;
            float hh, hl;
            split_bf16(hv, hh, hl);
            hhi_w[m * 136 + ltid] = __float2bfloat16(hh);
            hlo_w[m * 136 + ltid] = __float2bfloat16(hl);
        }
        // RAW: step-t h writes (buf (t+1)&1) visible to step-t+1 B reads
        asm volatile("bar.sync %0, 128;" :: "r"(bar) : "memory");
    }
}

// -------------------- launch -------------------------------------------------
extern "C" void kernel_launch(void* const* d_in, const int* in_sizes, int n_in,
                              void* d_out, int out_size) {
    (void)in_sizes; (void)n_in; (void)out_size;
    const float* x     = (const float*)d_in[0];
    const float* wi_w  = (const float*)d_in[1];
    const float* wi_b  = (const float*)d_in[2];
    const float* wf_w  = (const float*)d_in[3];
    const float* wf_b  = (const float*)d_in[4];
    const float* wo_w  = (const float*)d_in[5];
    const float* wo_b  = (const float*)d_in[6];
    const float* wc_w  = (const float*)d_in[7];
    const float* wc_b  = (const float*)d_in[8];
    const float* gcn_w = (const float*)d_in[9];
    const float* gcn_b = (const float*)d_in[10];
    float* out = (float*)d_out;

    const int smem_bytes = TOT_WORDS * 4;   // 231,424 B (~226 KB)
    cudaFuncSetAttribute(fused_kernel,
                         cudaFuncAttributeMaxDynamicSharedMemorySize, smem_bytes);

    fused_kernel<<<BATCH / GROUPS, 512, smem_bytes>>>(
        x, wi_w, wi_b, wf_w, wf_b, wo_w, wo_b, wc_w, wc_b,
        gcn_w, gcn_b, out);
}

// round 14
// speedup vs baseline: 1.1496x; 1.1496x over previous
#include <cuda_runtime.h>
#include <cuda_bf16.h>
#include <cstdint>

// ---------------------------------------------------------------------------
// GraphConvLSTM on GB300 — Round 14: single kernel, coalesced in-kernel gate
// projection (R13 fused the gate GEMM but with uncoalesced W reads; this
// round stages W through smem transposed, the proven gate_kernel pattern).
// Recurrence identical to R12.
// ---------------------------------------------------------------------------

#define BATCH   512
#define INDIM   256
#define HDIM    128
#define TSTEPS  100
#define NNODES  22
#define GROUPS  4

// smem word layout (4B words)
#define WPL_WORDS  (128 * 68)          // one W^T bf16 plane [j][kword], stride 68
#define HPL_WORDS  (24 * 68)           // one h bf16 plane [node][kword]
#define HBUF_BYTES (2 * HPL_WORDS * 4) // hi+lo pair, one buffer (13056 B)
#define P_STRIDE   28                  // p row stride: 112B, 16B-aligned, cf-free
#define P_WORDS    (128 * P_STRIDE)    // also hosts x staging (256 floats) at init
#define GRP_WORDS  (4 * HPL_WORDS + P_WORDS)              // 10112
#define TOT_WORDS  (2 * WPL_WORDS + GROUPS * GRP_WORDS)   // 57856 (226 KB)

// -------------------- clique-factored adjacency ------------------------------
__device__ constexpr int CLQ[5][6] = {
    {0,2,5,8,11,-1}, {0,1,4,7,10,-1}, {0,3,6,9,12,15},
    {9,14,17,19,21,-1}, {9,13,16,18,20,-1}
};
__device__ constexpr int CMASK[22] = {
    7,2,1,4,2,1,4,2,1,28,2,1,4,16,8,4,16,8,16,8,16,8
};
__device__ constexpr float CCNT[22] = {
    3.f,1.f,1.f,1.f,1.f,1.f,1.f,1.f,1.f,3.f,1.f,1.f,1.f,1.f,1.f,1.f,1.f,1.f,1.f,1.f,1.f,1.f
};
__device__ constexpr float DINV[22] = {
    0.2773500979f, 0.5f, 0.5f, 0.4472135955f, 0.5f, 0.5f, 0.4472135955f, 0.5f, 0.5f,
    0.2773500979f, 0.5f, 0.5f, 0.4472135955f, 0.5f, 0.5f, 0.4472135955f,
    0.5f, 0.5f, 0.5f, 0.5f, 0.5f, 0.5f
};

// -------------------- helpers ------------------------------------------------
__device__ __forceinline__ uint32_t pack_bf16(float a, float b) {
    __nv_bfloat162 v = __floats2bfloat162_rn(a, b);
    return *reinterpret_cast<uint32_t*>(&v);
}
__device__ __forceinline__ void split_bf16(float f, float& hi, float& lo) {
    __nv_bfloat16 h = __float2bfloat16(f);
    hi = __bfloat162float(h);
    lo = f - hi;
}
__device__ __forceinline__ float tanha(float x) {
    float r;
    asm("tanh.approx.f32 %0, %1;" : "=f"(r) : "f"(x));
    return r;
}
__device__ __forceinline__ float sig_h(float a) {   // sigmoid(2a)
    return fmaf(0.5f, tanha(a), 0.5f);
}
__device__ __forceinline__ uint32_t smem_u32(const void* p) {
    return static_cast<uint32_t>(__cvta_generic_to_shared(p));
}

#define MMA_BF16(D, A0, A1, A2, A3, B0, B1)                                    \
    asm volatile(                                                              \
        "mma.sync.aligned.m16n8k16.row.col.f32.bf16.bf16.f32 "                 \
        "{%0,%1,%2,%3}, {%4,%5,%6,%7}, {%8,%9}, {%0,%1,%2,%3};"                \
        : "+f"((D)[0]), "+f"((D)[1]), "+f"((D)[2]), "+f"((D)[3])               \
        : "r"(A0), "r"(A1), "r"(A2), "r"(A3), "r"(B0), "r"(B1))

#define LDSM_X4(R0, R1, R2, R3, ADDR)                                          \
    asm volatile(                                                              \
        "ldmatrix.sync.aligned.m8n8.x4.shared.b16 {%0,%1,%2,%3}, [%4];"        \
        : "=r"(R0), "=r"(R1), "=r"(R2), "=r"(R3) : "r"(ADDR))

// -------------------- fused: gates + recurrence -------------------------------
__global__ __launch_bounds__(512, 1) void fused_kernel(
    const float* __restrict__ x,
    const float* __restrict__ wi, const float* __restrict__ bi,
    const float* __restrict__ wf, const float* __restrict__ bf,
    const float* __restrict__ wo, const float* __restrict__ bo,
    const float* __restrict__ wc, const float* __restrict__ bc,
    const float* __restrict__ gw,
    const float* __restrict__ gb,
    float* __restrict__ out)
{
    extern __shared__ uint32_t smw[];
    uint32_t* wth = smw;                  // W^T hi plane [j][kword], stride 68
    uint32_t* wtl = smw + WPL_WORDS;      // W^T lo plane

    const int tid  = threadIdx.x;
    const int g    = tid >> 7;            // group 0..3
    const int ltid = tid & 127;           // column j
    const int lane = tid & 31;
    const int wig  = ltid >> 5;
    const int b    = blockIdx.x * GROUPS + g;

    // group layout: [hhi0|hlo0|hhi1|hlo1|ps]
    uint32_t* grp  = smw + 2 * WPL_WORDS + g * GRP_WORDS;
    uint32_t* hbuf = grp;                                   // 4 h planes
    float*    ps   = reinterpret_cast<float*>(grp + 4 * HPL_WORDS);

    // ---------- phase 0: stage x[b] into this group's ps region --------------
    reinterpret_cast<float2*>(ps)[ltid] =
        reinterpret_cast<const float2*>(x + (size_t)b * INDIM)[ltid];
    __syncthreads();

    // ---------- phase 1: gate projection (coalesced W staging) ---------------
    // Scratch: the (not yet initialized) W^T plane region. Chunk = 64 k-cols
    // of one gate's W, stored transposed ws[kk][j], stride 129 (cf-free).
    // Single fp32 chain per gate in ascending k: bit-identical to R12 gates.
    float xi, xf, xo, xc;
    {
        float* wsc = reinterpret_cast<float*>(smw);      // 64 KB scratch
        const float* wptr[4] = {wi, wf, wo, wc};
        float accg[4];
#pragma unroll
        for (int gate = 0; gate < 4; gate++) {
            float a = 0.f;
            for (int kc = 0; kc < 4; kc++) {             // 4 chunks of 64 k
                __syncthreads();
                // stage: w[j][kc*64 + kk] -> wsc[kk*129 + j]   (LDG.128 coalesced)
                for (int i = tid; i < 128 * 16; i += 512) {
                    int j  = i >> 4;                      // row
                    int k4 = i & 15;                      // float4 within chunk
                    float4 v = reinterpret_cast<const float4*>(
                        wptr[gate] + j * INDIM + kc * 64)[k4];
                    wsc[(k4 * 4 + 0) * 129 + j] = v.x;
                    wsc[(k4 * 4 + 1) * 129 + j] = v.y;
                    wsc[(k4 * 4 + 2) * 129 + j] = v.z;
                    wsc[(k4 * 4 + 3) * 129 + j] = v.w;
                }
                __syncthreads();
                const float4* xs4 = reinterpret_cast<const float4*>(ps + kc * 64);
#pragma unroll 4
                for (int k4 = 0; k4 < 16; k4++) {
                    float4 xv = xs4[k4];
                    a = fmaf(xv.x, wsc[(k4 * 4 + 0) * 129 + ltid], a);
                    a = fmaf(xv.y, wsc[(k4 * 4 + 1) * 129 + ltid], a);
                    a = fmaf(xv.z, wsc[(k4 * 4 + 2) * 129 + ltid], a);
                    a = fmaf(xv.w, wsc[(k4 * 4 + 3) * 129 + ltid], a);
                }
            }
            accg[gate] = a;
        }
        float gbv = gb[ltid];
        xi = 0.5f * ((accg[0] + bi[ltid]) + gbv);
        xf = 0.5f * ((accg[1] + bf[ltid]) + gbv);
        xo = 0.5f * ((accg[2] + bo[ltid]) + gbv);
        xc = (accg[3] + bc[ltid]) + gbv;
    }
    __syncthreads();   // gate scratch fully consumed before W^T plane init

    // ---------- phase 2: W^T bf16 planes + zero h buffers ---------------------
    for (int idx = tid; idx < 128 * 64; idx += 512) {
        int jr = idx >> 6;
        int k2 = idx & 63;
        int k  = 2 * k2;
        float w0 = gw[k * HDIM + jr];
        float w1 = gw[(k + 1) * HDIM + jr];
        float h0, l0, h1, l1;
        split_bf16(w0, h0, l0);
        split_bf16(w1, h1, l1);
        wth[jr * 68 + k2] = pack_bf16(h0, h1);
        wtl[jr * 68 + k2] = pack_bf16(l0, l1);
    }
    for (int i = tid; i < GROUPS * 4 * HPL_WORDS; i += 512) {
        int gg = i / (4 * HPL_WORDS);
        int o  = i - gg * (4 * HPL_WORDS);
        smw[2 * WPL_WORDS + gg * GRP_WORDS + o] = 0u;
    }
    __syncthreads();

    // ---------- persistent per-thread state ----------
    float c[NNODES];
#pragma unroll
    for (int m = 0; m < NNODES; m++) c[m] = 0.f;

    // A-fragment ldmatrix bases: [plane][mt]
    const int lq  = lane >> 2;
    const int kw  = lane & 3;
    const int wof = wig * 32;
    uint32_t a_base[2][2];
    {
        int arow = (lane & 7) + ((lane >> 3) & 1) * 8;
        int acol = ((lane >> 4) & 1) * 4;
#pragma unroll
        for (int p = 0; p < 2; p++) {
            const uint32_t* pl = p ? wtl : wth;
#pragma unroll
            for (int mt = 0; mt < 2; mt++)
                a_base[p][mt] = smem_u32(pl + (wof + mt * 16 + arow) * 68 + acol);
        }
    }
    // B-fragment ldmatrix bases for buffer 0: [plane][nt]; buffer 1 = +HBUF_BYTES
    uint32_t b_base[2][3];
    {
        int brow  = lane & 7;
        int bhalf = lane >> 3;            // 0..3
#pragma unroll
        for (int p = 0; p < 2; p++) {
            const uint32_t* pl = hbuf + p * HPL_WORDS;   // hhi0 / hlo0
#pragma unroll
            for (int nt = 0; nt < 3; nt++)
                b_base[p][nt] = smem_u32(pl + (nt * 8 + brow) * 68) + bhalf * 16;
        }
    }

    const int bar = g + 1;

    // phase stagger: groups drift anti-phase so HMMA and MUFU bursts overlap
    __nanosleep(g * 2000u);

    for (int t = 0; t < TSTEPS; t++) {
        const uint32_t rbuf = (uint32_t)(t & 1) * HBUF_BYTES;      // read buffer
        uint32_t* whbuf = hbuf + ((t + 1) & 1) * 2 * HPL_WORDS;    // write buffer
        __nv_bfloat16* hhi_w = reinterpret_cast<__nv_bfloat16*>(whbuf);
        __nv_bfloat16* hlo_w = reinterpret_cast<__nv_bfloat16*>(whbuf + HPL_WORDS);

        // ---- mma phase: p^T(2mt x 3nt) = W^T(hi/lo) @ h(hi/lo), K=128 ----
        float acc[2][3][4];
#pragma unroll
        for (int mt = 0; mt < 2; mt++)
#pragma unroll
            for (int nt = 0; nt < 3; nt++)
#pragma unroll
                for (int q = 0; q < 4; q++) acc[mt][nt][q] = 0.f;

#pragma unroll
        for (int kp = 0; kp < 4; kp++) {          // pairs of k-steps
            uint32_t bh[3][4], bl[3][4];
#pragma unroll
            for (int nt = 0; nt < 3; nt++) {
                LDSM_X4(bh[nt][0], bh[nt][1], bh[nt][2], bh[nt][3],
                        b_base[0][nt] + rbuf + kp * 64);
                LDSM_X4(bl[nt][0], bl[nt][1], bl[nt][2], bl[nt][3],
                        b_base[1][nt] + rbuf + kp * 64);
            }
#pragma unroll
            for (int hf = 0; hf < 2; hf++) {      // kt = 2*kp + hf
                const uint32_t koff = (2 * kp + hf) * 32;
                uint32_t ah[2][4], al[2][4];
#pragma unroll
                for (int mt = 0; mt < 2; mt++) {
                    LDSM_X4(ah[mt][0], ah[mt][1], ah[mt][2], ah[mt][3],
                            a_base[0][mt] + koff);
                    LDSM_X4(al[mt][0], al[mt][1], al[mt][2], al[mt][3],
                            a_base[1][mt] + koff);
                }
#pragma unroll
                for (int nt = 0; nt < 3; nt++) {
                    uint32_t b0h = bh[nt][hf * 2], b1h = bh[nt][hf * 2 + 1];
                    uint32_t b0l = bl[nt][hf * 2], b1l = bl[nt][hf * 2 + 1];
#pragma unroll
                    for (int mt = 0; mt < 2; mt++) {
                        MMA_BF16(acc[mt][nt], ah[mt][0], ah[mt][1], ah[mt][2], ah[mt][3], b0h, b1h);
                        MMA_BF16(acc[mt][nt], ah[mt][0], ah[mt][1], ah[mt][2], ah[mt][3], b0l, b1l);
                        MMA_BF16(acc[mt][nt], al[mt][0], al[mt][1], al[mt][2], al[mt][3], b0h, b1h);
                    }
                }
            }
        }

        // ---- spill p fragments: ps[j][node] (intra-warp rows) ----
#pragma unroll
        for (int mt = 0; mt < 2; mt++) {
            int j0 = wof + mt * 16 + lq;
            int j1 = j0 + 8;
#pragma unroll
            for (int nt = 0; nt < 3; nt++) {
                int n0 = nt * 8 + (kw << 1);
                *reinterpret_cast<float2*>(&ps[j0 * P_STRIDE + n0]) =
                    make_float2(acc[mt][nt][0], acc[mt][nt][1]);
                *reinterpret_cast<float2*>(&ps[j1 * P_STRIDE + n0]) =
                    make_float2(acc[mt][nt][2], acc[mt][nt][3]);
            }
        }
        // p exchange is warp-local (warp wig owns ps rows [32*wig, 32*wig+32))
        __syncwarp();

        // ---- combine + epilogue: thread owns column j = ltid ----
        float p[NNODES];
        {
            const float4* pv = reinterpret_cast<const float4*>(&ps[ltid * P_STRIDE]);
#pragma unroll
            for (int q = 0; q < 5; q++) {
                float4 v = pv[q];
                p[q * 4 + 0] = v.x; p[q * 4 + 1] = v.y;
                if (q * 4 + 2 < NNODES) p[q * 4 + 2] = v.z;
                if (q * 4 + 3 < NNODES) p[q * 4 + 3] = v.w;
            }
            float2 v2 = *reinterpret_cast<const float2*>(&ps[ltid * P_STRIDE + 20]);
            p[20] = v2.x; p[21] = v2.y;
        }

        // clique sums
        float S[5];
#pragma unroll
        for (int cq = 0; cq < 5; cq++) {
            float s = 0.f;
#pragma unroll
            for (int e = 0; e < 6; e++) {
                if (CLQ[cq][e] >= 0) {
                    const int n = CLQ[cq][e];
                    s = fmaf(DINV[n], p[n], s);
                }
            }
            S[cq] = s;
        }

        float* ob = out + (((size_t)b * TSTEPS + t) * NNODES) * HDIM + ltid;
#pragma unroll
        for (int m = 0; m < NNODES; m++) {
            float s = 0.f;
#pragma unroll
            for (int cq = 0; cq < 5; cq++)
                if ((CMASK[m] >> cq) & 1) s += S[cq];
            float gacc = DINV[m] * (s - CCNT[m] * DINV[m] * p[m]);

            float hd = 0.5f * gacc;
            float it = sig_h(xi + hd);
            float ft = sig_h(xf + hd);
            float ot = sig_h(xo + hd);
            float ct = tanha(xc + gacc);
            float cn = fmaf(ft, c[m], it * ct);
            c[m] = cn;
            float hv = ot * tanha(cn);
            ob[m * HDIM] = hv;
            float hh, hl;
            split_bf16(hv, hh, hl);
            hhi_w[m * 136 + ltid] = __float2bfloat16(hh);
            hlo_w[m * 136 + ltid] = __float2bfloat16(hl);
        }
        // RAW: step-t h writes (buf (t+1)&1) visible to step-t+1 B reads
        asm volatile("bar.sync %0, 128;" :: "r"(bar) : "memory");
    }
}

// -------------------- launch -------------------------------------------------
extern "C" void kernel_launch(void* const* d_in, const int* in_sizes, int n_in,
                              void* d_out, int out_size) {
    (void)in_sizes; (void)n_in; (void)out_size;
    const float* x     = (const float*)d_in[0];
    const float* wi_w  = (const float*)d_in[1];
    const float* wi_b  = (const float*)d_in[2];
    const float* wf_w  = (const float*)d_in[3];
    const float* wf_b  = (const float*)d_in[4];
    const float* wo_w  = (const float*)d_in[5];
    const float* wo_b  = (const float*)d_in[6];
    const float* wc_w  = (const float*)d_in[7];
    const float* wc_b  = (const float*)d_in[8];
    const float* gcn_w = (const float*)d_in[9];
    const float* gcn_b = (const float*)d_in[10];
    float* out = (float*)d_out;

    const int smem_bytes = TOT_WORDS * 4;   // 231,424 B (~226 KB)
    cudaFuncSetAttribute(fused_kernel,
                         cudaFuncAttributeMaxDynamicSharedMemorySize, smem_bytes);

    fused_kernel<<<BATCH / GROUPS, 512, smem_bytes>>>(
        x, wi_w, wi_b, wf_w, wf_b, wo_w, wo_b, wc_w, wc_b,
        gcn_w, gcn_b, out);
}